// round 1
// baseline (speedup 1.0000x reference)
#include <cuda_runtime.h>
#include <cstdint>

// GriddingDistance: trilinear scatter of two point clouds into voxel grids.
// SCALE=128, L=131, V=L^3=2248091, B=16, N=32768.
// Output: [pred_grid (B*V floats) | gt_grid (B*V floats)] = 71,938,912 floats.

#define SCALE_F 64.0f      // SCALE * 0.5
#define GRID_L  131
#define GRID_V  (GRID_L * GRID_L * GRID_L)   // 2248091
#define BATCH   16
#define NPTS    32768

// Per-axis integer min of floor(scaled coords), shared across both clouds.
__device__ int g_min[3];

__global__ void reset_min_kernel() {
    if (threadIdx.x < 3) g_min[threadIdx.x] = 0x7fffffff;
}

// floor(min(p)) == min(floor(p)) since floor is monotone -> integer reduction.
__global__ void min_kernel(const float* __restrict__ pred,
                           const float* __restrict__ gt) {
    const int total = BATCH * NPTS;
    int tid = blockIdx.x * blockDim.x + threadIdx.x;
    int stride = gridDim.x * blockDim.x;

    int mn0 = 0x7fffffff, mn1 = 0x7fffffff, mn2 = 0x7fffffff;
    for (int i = tid; i < total; i += stride) {
        const float* p = pred + 3 * i;
        const float* g = gt   + 3 * i;
        int p0 = (int)floorf(p[0] * SCALE_F);
        int p1 = (int)floorf(p[1] * SCALE_F);
        int p2 = (int)floorf(p[2] * SCALE_F);
        int g0 = (int)floorf(g[0] * SCALE_F);
        int g1 = (int)floorf(g[1] * SCALE_F);
        int g2 = (int)floorf(g[2] * SCALE_F);
        mn0 = min(mn0, min(p0, g0));
        mn1 = min(mn1, min(p1, g1));
        mn2 = min(mn2, min(p2, g2));
    }
    // warp reduce
    #pragma unroll
    for (int off = 16; off > 0; off >>= 1) {
        mn0 = min(mn0, __shfl_xor_sync(0xffffffffu, mn0, off));
        mn1 = min(mn1, __shfl_xor_sync(0xffffffffu, mn1, off));
        mn2 = min(mn2, __shfl_xor_sync(0xffffffffu, mn2, off));
    }
    if ((threadIdx.x & 31) == 0) {
        atomicMin(&g_min[0], mn0);
        atomicMin(&g_min[1], mn1);
        atomicMin(&g_min[2], mn2);
    }
}

// One thread per point, covering both clouds (tid in [0, 2*B*N)).
__global__ void scatter_kernel(const float* __restrict__ pred,
                               const float* __restrict__ gt,
                               float* __restrict__ out) {
    const int per_cloud = BATCH * NPTS;
    int tid = blockIdx.x * blockDim.x + threadIdx.x;
    if (tid >= 2 * per_cloud) return;

    int cid = tid / per_cloud;       // 0 = pred, 1 = gt
    int pi  = tid - cid * per_cloud; // point index within cloud
    int b   = pi / NPTS;

    const float* cloud = (cid == 0) ? pred : gt;
    const float* p = cloud + 3 * pi;

    float x = p[0] * SCALE_F;
    float y = p[1] * SCALE_F;
    float z = p[2] * SCALE_F;

    // padding mask: scaled sum == 0 -> dropped (scaling by 2^6 is exact)
    if (x + y + z == 0.0f) return;

    float fx = floorf(x), fy = floorf(y), fz = floorf(z);
    float ax = x - fx, ay = y - fy, az = z - fz;  // frac in [0,1)
    float bx = 1.0f - ax, by = 1.0f - ay, bz = 1.0f - az;

    // min_corner = g_min - 1
    int ix = (int)fx - (g_min[0] - 1);
    int iy = (int)fy - (g_min[1] - 1);
    int iz = (int)fz - (g_min[2] - 1);

    int base = (cid * BATCH + b) * GRID_V
             + (ix * GRID_L + iy) * GRID_L + iz;
    float* g = out + base;

    float w00 = bx * by;   // (0,0,*)
    float w01 = bx * ay;   // (0,1,*)
    float w10 = ax * by;   // (1,0,*)
    float w11 = ax * ay;   // (1,1,*)

    // 4 adjacent pairs -> ~4 dirty sectors per point
    atomicAdd(g + 0,                       w00 * bz);
    atomicAdd(g + 1,                       w00 * az);
    atomicAdd(g + GRID_L,                  w01 * bz);
    atomicAdd(g + GRID_L + 1,              w01 * az);
    atomicAdd(g + GRID_L * GRID_L,         w10 * bz);
    atomicAdd(g + GRID_L * GRID_L + 1,     w10 * az);
    atomicAdd(g + GRID_L * GRID_L + GRID_L,     w11 * bz);
    atomicAdd(g + GRID_L * GRID_L + GRID_L + 1, w11 * az);
}

extern "C" void kernel_launch(void* const* d_in, const int* in_sizes, int n_in,
                              void* d_out, int out_size) {
    const float* pred = (const float*)d_in[0];
    const float* gt   = (const float*)d_in[1];
    float* out        = (float*)d_out;

    // zero the full output grid (poisoned before timing)
    cudaMemsetAsync(d_out, 0, (size_t)out_size * sizeof(float), 0);

    reset_min_kernel<<<1, 32>>>();
    min_kernel<<<1024, 256>>>(pred, gt);

    int total = 2 * BATCH * NPTS;
    scatter_kernel<<<(total + 255) / 256, 256>>>(pred, gt, out);
}

// round 2
// speedup vs baseline: 1.0912x; 1.0912x over previous
#include <cuda_runtime.h>
#include <cstdint>

// GriddingDistance: trilinear scatter of two point clouds into voxel grids.
// SCALE=128, L=131, V=L^3=2248091, B=16, N=32768.
// Output: [pred_grid (B*V floats) | gt_grid (B*V floats)] = 71,938,912 floats.

#define SCALE_F   64.0f            // SCALE * 0.5
#define GRID_L    131
#define GRID_L2   (GRID_L * GRID_L)
#define GRID_V    (GRID_L * GRID_L * GRID_L)   // 2248091
#define BATCH     16
#define NPTS      32768
#define PER_CLOUD (BATCH * NPTS)               // 524288

// Per-axis integer min of floor(scaled coords), shared across both clouds.
// Statically initialized for the FIRST call; the trailing reset kernel
// restores it after every call so graph replays are deterministic.
__device__ int g_min[3] = {0x7fffffff, 0x7fffffff, 0x7fffffff};

__global__ void reset_min_kernel() {
    if (threadIdx.x < 3) g_min[threadIdx.x] = 0x7fffffff;
}

// Fused: per-axis integer min over BOTH clouds (floor is monotone, so
// floor(min) == min(floor) -> pure integer atomicMin), PLUS zeroing the
// whole output grid with float4 stores.
__global__ void prep_kernel(const float* __restrict__ pred,
                            const float* __restrict__ gt,
                            float4* __restrict__ out4, int n4,
                            float* __restrict__ out, int n_total) {
    const int gtid = blockIdx.x * blockDim.x + threadIdx.x;
    const int gsz  = gridDim.x * blockDim.x;

    // ---- min over all 2*B*N points (padding points included, per reference)
    int mn0 = 0x7fffffff, mn1 = 0x7fffffff, mn2 = 0x7fffffff;
    for (int i = gtid; i < 2 * PER_CLOUD; i += gsz) {
        const float* p = (i < PER_CLOUD) ? (pred + 3 * i)
                                         : (gt + 3 * (i - PER_CLOUD));
        int c0 = (int)floorf(p[0] * SCALE_F);
        int c1 = (int)floorf(p[1] * SCALE_F);
        int c2 = (int)floorf(p[2] * SCALE_F);
        mn0 = min(mn0, c0);
        mn1 = min(mn1, c1);
        mn2 = min(mn2, c2);
    }
    #pragma unroll
    for (int off = 16; off > 0; off >>= 1) {
        mn0 = min(mn0, __shfl_xor_sync(0xffffffffu, mn0, off));
        mn1 = min(mn1, __shfl_xor_sync(0xffffffffu, mn1, off));
        mn2 = min(mn2, __shfl_xor_sync(0xffffffffu, mn2, off));
    }
    if ((threadIdx.x & 31) == 0) {
        atomicMin(&g_min[0], mn0);
        atomicMin(&g_min[1], mn1);
        atomicMin(&g_min[2], mn2);
    }

    // ---- zero the output grid (bulk float4 + scalar tail)
    const float4 z4 = make_float4(0.f, 0.f, 0.f, 0.f);
    for (int i = gtid; i < n4; i += gsz) out4[i] = z4;
    for (int i = 4 * n4 + gtid; i < n_total; i += gsz) out[i] = 0.f;
}

// Trilinear scatter of one cloud into its grid half. One thread per point.
__global__ void scatter_kernel(const float* __restrict__ cloud,
                               float* __restrict__ out) {
    int tid = blockIdx.x * blockDim.x + threadIdx.x;
    if (tid >= PER_CLOUD) return;

    int b = tid >> 15;               // tid / NPTS
    const float* p = cloud + 3 * tid;

    float x = p[0] * SCALE_F;
    float y = p[1] * SCALE_F;
    float z = p[2] * SCALE_F;

    // padding mask: scaled sum == 0 -> dropped (x64 scaling is exact)
    if (x + y + z == 0.0f) return;

    float fx = floorf(x), fy = floorf(y), fz = floorf(z);
    float ax = x - fx, ay = y - fy, az = z - fz;   // frac in [0,1)
    float bx = 1.0f - ax, by = 1.0f - ay, bz = 1.0f - az;

    // min_corner = g_min - 1
    int ix = (int)fx - (g_min[0] - 1);
    int iy = (int)fy - (g_min[1] - 1);
    int iz = (int)fz - (g_min[2] - 1);

    float* g = out + (size_t)b * GRID_V + (ix * GRID_L + iy) * GRID_L + iz;

    float w00 = bx * by;   // corner (0,0,*)
    float w01 = bx * ay;   // corner (0,1,*)
    float w10 = ax * by;   // corner (1,0,*)
    float w11 = ax * ay;   // corner (1,1,*)

    // z-pairs are adjacent; L is odd, so exactly 2 of the 4 pairs are
    // 8B-aligned -> use 64-bit vector reductions for those (sm_90+).
    bool aligned0 = ((reinterpret_cast<uintptr_t>(g) & 7u) == 0);
    if (aligned0) {
        atomicAdd(reinterpret_cast<float2*>(g),
                  make_float2(w00 * bz, w00 * az));
        atomicAdd(reinterpret_cast<float2*>(g + GRID_L2 + GRID_L),
                  make_float2(w11 * bz, w11 * az));
        atomicAdd(g + GRID_L,      w01 * bz);
        atomicAdd(g + GRID_L + 1,  w01 * az);
        atomicAdd(g + GRID_L2,     w10 * bz);
        atomicAdd(g + GRID_L2 + 1, w10 * az);
    } else {
        atomicAdd(g + 0, w00 * bz);
        atomicAdd(g + 1, w00 * az);
        atomicAdd(reinterpret_cast<float2*>(g + GRID_L),
                  make_float2(w01 * bz, w01 * az));
        atomicAdd(reinterpret_cast<float2*>(g + GRID_L2),
                  make_float2(w10 * bz, w10 * az));
        atomicAdd(g + GRID_L2 + GRID_L,     w11 * bz);
        atomicAdd(g + GRID_L2 + GRID_L + 1, w11 * az);
    }
}

extern "C" void kernel_launch(void* const* d_in, const int* in_sizes, int n_in,
                              void* d_out, int out_size) {
    const float* pred = (const float*)d_in[0];
    const float* gt   = (const float*)d_in[1];
    float* out        = (float*)d_out;

    int n4 = out_size >> 2;

    // 1) fused min + zero
    prep_kernel<<<2048, 256>>>(pred, gt, (float4*)d_out, n4, out, out_size);

    // 2) scatter pred, 3) scatter gt (split so ncu -s 5 samples a scatter)
    scatter_kernel<<<PER_CLOUD / 256, 256>>>(pred, out);
    scatter_kernel<<<PER_CLOUD / 256, 256>>>(gt, out + (size_t)BATCH * GRID_V);

    // 4) restore g_min for the next (deterministic) replay
    reset_min_kernel<<<1, 32>>>();
}